// round 1
// baseline (speedup 1.0000x reference)
#include <cuda_runtime.h>

#define NB   32
#define CC   512
#define LL   512
#define KG   10
#define VK   8

// Scratch (no allocations allowed)
__device__ float g_a [NB * KG * LL];   // softmax assignments [n][k][l]
__device__ float g_ax[NB * VK * CC];   // assign_x for k<8    [n][k][c]

typedef unsigned long long u64;

__device__ __forceinline__ u64 pack2(float lo, float hi) {
    u64 r; asm("mov.b64 %0,{%1,%2};" : "=l"(r) : "f"(lo), "f"(hi)); return r;
}
__device__ __forceinline__ void unpack2(u64 v, float& lo, float& hi) {
    asm("mov.b64 {%0,%1},%2;" : "=f"(lo), "=f"(hi) : "l"(v));
}
__device__ __forceinline__ u64 ffma2(u64 a, u64 b, u64 c) {
    u64 d; asm("fma.rn.f32x2 %0,%1,%2,%3;" : "=l"(d) : "l"(a), "l"(b), "l"(c)); return d;
}

// ---------------------------------------------------------------------------
// K1: logits = W @ x + b, softmax over k, write a[n][k][l]
// grid (L/128, N), block 128. Thread owns one l; k packed in f32x2 pairs.
// ---------------------------------------------------------------------------
__global__ __launch_bounds__(128) void k1_logits_softmax(
    const float* __restrict__ x, const float* __restrict__ w,
    const float* __restrict__ b)
{
    __shared__ float wsh[CC * 12];   // [c][k] padded to 12 floats (48B rows, 16B aligned)
    const int tid = threadIdx.x;
    const int n   = blockIdx.y;
    const int l   = blockIdx.x * 128 + tid;

    for (int i = tid; i < KG * CC; i += 128) {
        int k = i >> 9, c = i & (CC - 1);
        wsh[c * 12 + k] = w[i];
    }
    __syncthreads();

    u64 acc[5];
#pragma unroll
    for (int p = 0; p < 5; p++) acc[p] = pack2(__ldg(b + 2 * p), __ldg(b + 2 * p + 1));

    const float* xp = x + (size_t)n * CC * LL + l;
#pragma unroll 4
    for (int c = 0; c < CC; c++) {
        float xv = xp[c * LL];
        u64 xd = pack2(xv, xv);
        const float* wr = wsh + c * 12;
        u64 w0 = *(const u64*)(wr + 0);
        u64 w1 = *(const u64*)(wr + 2);
        u64 w2 = *(const u64*)(wr + 4);
        u64 w3 = *(const u64*)(wr + 6);
        u64 w4 = *(const u64*)(wr + 8);
        acc[0] = ffma2(w0, xd, acc[0]);
        acc[1] = ffma2(w1, xd, acc[1]);
        acc[2] = ffma2(w2, xd, acc[2]);
        acc[3] = ffma2(w3, xd, acc[3]);
        acc[4] = ffma2(w4, xd, acc[4]);
    }

    float lg[KG];
#pragma unroll
    for (int p = 0; p < 5; p++) unpack2(acc[p], lg[2 * p], lg[2 * p + 1]);

    float m = lg[0];
#pragma unroll
    for (int k = 1; k < KG; k++) m = fmaxf(m, lg[k]);
    float s = 0.f;
#pragma unroll
    for (int k = 0; k < KG; k++) { lg[k] = __expf(lg[k] - m); s += lg[k]; }
    float inv = 1.f / s;

    float* ap = g_a + ((size_t)n * KG) * LL + l;
#pragma unroll
    for (int k = 0; k < KG; k++) ap[k * LL] = lg[k] * inv;
}

// ---------------------------------------------------------------------------
// K2: assign_x[n][k][c] = sum_l a[n][k][l] * x[n][c][l], k<8.
// grid (C/64, N), block 256 (8 warps). Warp owns 8 c's (two 4-c register
// groups). l packed in f32x2 pairs; a staged in smem, reused 4x per load.
// ---------------------------------------------------------------------------
__global__ __launch_bounds__(256) void k2_assign(const float* __restrict__ x)
{
    __shared__ float ash[VK * LL];   // 16 KB
    const int tid  = threadIdx.x;
    const int lane = tid & 31;
    const int warp = tid >> 5;
    const int n    = blockIdx.y;

    for (int i = tid; i < VK * LL; i += 256) ash[i] = g_a[(size_t)n * KG * LL + i];
    __syncthreads();

    const int cbase = blockIdx.x * 64 + warp * 8;

#pragma unroll 1
    for (int g = 0; g < 2; g++) {
        const int c0 = cbase + g * 4;
        u64 acc[4][8];
#pragma unroll
        for (int ci = 0; ci < 4; ci++)
#pragma unroll
            for (int k = 0; k < 8; k++) acc[ci][k] = 0ull;

        const float* xb = x + ((size_t)n * CC + c0) * LL;

#pragma unroll 1
        for (int j = 0; j < 8; j++) {
            const int l0 = j * 64 + lane * 2;
            u64 a2[8];
#pragma unroll
            for (int k = 0; k < 8; k++) a2[k] = *(const u64*)(ash + k * LL + l0);
#pragma unroll
            for (int ci = 0; ci < 4; ci++) {
                u64 x2 = *(const u64*)(xb + ci * LL + l0);
#pragma unroll
                for (int k = 0; k < 8; k++) acc[ci][k] = ffma2(a2[k], x2, acc[ci][k]);
            }
        }

#pragma unroll
        for (int ci = 0; ci < 4; ci++) {
#pragma unroll
            for (int k = 0; k < 8; k++) {
                float lo, hi; unpack2(acc[ci][k], lo, hi);
                float v = lo + hi;
#pragma unroll
                for (int off = 16; off; off >>= 1)
                    v += __shfl_down_sync(0xffffffffu, v, off);
                if (lane == 0)
                    g_ax[((size_t)n * VK + k) * CC + c0 + ci] = v;
            }
        }
    }
}

// ---------------------------------------------------------------------------
// K3: assign_sum, residual vs centers, per-cluster L2 norm, global L2 norm.
// grid N, block 512 (thread = c).
// ---------------------------------------------------------------------------
__global__ __launch_bounds__(512) void k3_epilogue(
    const float* __restrict__ centers, float* __restrict__ out)
{
    __shared__ float asum_sh[VK];
    __shared__ float part[16][VK];
    __shared__ float scale_sh[VK];

    const int tid  = threadIdx.x;
    const int lane = tid & 31;
    const int warp = tid >> 5;
    const int n    = blockIdx.x;

    // assign_sum[k] = sum_l a[n][k][l], one warp per k
    if (warp < VK) {
        const float* ap = g_a + ((size_t)n * KG + warp) * LL;
        float s = 0.f;
        for (int i = lane; i < LL; i += 32) s += ap[i];
#pragma unroll
        for (int off = 16; off; off >>= 1) s += __shfl_down_sync(0xffffffffu, s, off);
        if (lane == 0) asum_sh[warp] = s;
    }
    __syncthreads();

    const int c = tid;
    float r[VK];
#pragma unroll
    for (int k = 0; k < VK; k++) {
        r[k] = g_ax[((size_t)n * VK + k) * CC + c] - asum_sh[k] * centers[k * CC + c];
        float v = r[k] * r[k];
#pragma unroll
        for (int off = 16; off; off >>= 1) v += __shfl_down_sync(0xffffffffu, v, off);
        if (lane == 0) part[warp][k] = v;
    }
    __syncthreads();

    if (tid == 0) {
        float vlad = 0.f, sc[VK];
#pragma unroll
        for (int k = 0; k < VK; k++) {
            float ss = 0.f;
            for (int w = 0; w < 16; w++) ss += part[w][k];
            float nm = sqrtf(ss);
            float s1 = 1.f / fmaxf(nm, 1e-12f);
            sc[k] = s1;
            vlad += ss * s1 * s1;
        }
        float fs = 1.f / fmaxf(sqrtf(vlad), 1e-12f);
#pragma unroll
        for (int k = 0; k < VK; k++) scale_sh[k] = sc[k] * fs;
    }
    __syncthreads();

#pragma unroll
    for (int k = 0; k < VK; k++)
        out[(size_t)n * VK * CC + k * CC + c] = r[k] * scale_sh[k];
}

// ---------------------------------------------------------------------------
extern "C" void kernel_launch(void* const* d_in, const int* in_sizes, int n_in,
                              void* d_out, int out_size)
{
    const float* x       = (const float*)d_in[0];  // [32,512,16,32]
    const float* conv_w  = (const float*)d_in[1];  // [10,512]
    const float* conv_b  = (const float*)d_in[2];  // [10]
    const float* centers = (const float*)d_in[3];  // [10,512]
    float* out = (float*)d_out;                    // [32, 4096]

    k1_logits_softmax<<<dim3(LL / 128, NB), 128>>>(x, conv_w, conv_b);
    k2_assign        <<<dim3(CC / 64,  NB), 256>>>(x);
    k3_epilogue      <<<NB, 512>>>(centers, out);
}

// round 4
// speedup vs baseline: 1.5182x; 1.5182x over previous
#include <cuda_runtime.h>

#define NB   32
#define CC   512
#define LL   512
#define KG   10
#define VK   8
#define CS   4
#define CT   (CC/CS)   // 128

// Scratch (no allocations allowed)
__device__ float g_part[NB * CS * KG * LL];   // partial logits [n][cs][k][l]
__device__ float g_a   [NB * VK * LL];        // softmax assignments, k<8 [n][k][l]
__device__ float g_asum[NB * 2 * VK];         // per-half assign_sum partials
__device__ float g_axp [2 * NB * VK * CC];    // assign_x partials per l-half

typedef unsigned long long u64;

__device__ __forceinline__ u64 pack2(float lo, float hi) {
    u64 r; asm("mov.b64 %0,{%1,%2};" : "=l"(r) : "f"(lo), "f"(hi)); return r;
}
__device__ __forceinline__ void unpack2(u64 v, float& lo, float& hi) {
    asm("mov.b64 {%0,%1},%2;" : "=f"(lo), "=f"(hi) : "l"(v));
}
__device__ __forceinline__ u64 ffma2(u64 a, u64 b, u64 c) {
    u64 d; asm("fma.rn.f32x2 %0,%1,%2,%3;" : "=l"(d) : "l"(a), "l"(b), "l"(c)); return d;
}

// ---------------------------------------------------------------------------
// K1: partial logits over a 128-c slice. grid (L/128, N, CS), block 128.
// Explicit 8-wide load batching for MLP.
// ---------------------------------------------------------------------------
__global__ __launch_bounds__(128) void k1_partial(
    const float* __restrict__ x, const float* __restrict__ w)
{
    __shared__ float wsh[CT * 12];   // [c][k], 12-float padded rows
    const int tid = threadIdx.x;
    const int n   = blockIdx.y;
    const int cs  = blockIdx.z;
    const int l   = blockIdx.x * 128 + tid;
    const int c0  = cs * CT;

    for (int i = tid; i < KG * CT; i += 128) {
        int k = i >> 7, c = i & (CT - 1);
        wsh[c * 12 + k] = w[k * CC + c0 + c];
    }
    __syncthreads();

    u64 acc[5];
#pragma unroll
    for (int p = 0; p < 5; p++) acc[p] = 0ull;

    const float* xp = x + ((size_t)n * CC + c0) * LL + l;
#pragma unroll 1
    for (int cb = 0; cb < CT; cb += 8) {
        float xv[8];
#pragma unroll
        for (int i = 0; i < 8; i++) xv[i] = xp[(cb + i) * LL];
#pragma unroll
        for (int i = 0; i < 8; i++) {
            u64 xd = pack2(xv[i], xv[i]);
            const float* wr = wsh + (cb + i) * 12;
            acc[0] = ffma2(*(const u64*)(wr + 0), xd, acc[0]);
            acc[1] = ffma2(*(const u64*)(wr + 2), xd, acc[1]);
            acc[2] = ffma2(*(const u64*)(wr + 4), xd, acc[2]);
            acc[3] = ffma2(*(const u64*)(wr + 6), xd, acc[3]);
            acc[4] = ffma2(*(const u64*)(wr + 8), xd, acc[4]);
        }
    }

    float lg[KG];
#pragma unroll
    for (int p = 0; p < 5; p++) unpack2(acc[p], lg[2 * p], lg[2 * p + 1]);

    float* pp = g_part + (((size_t)n * CS + cs) * KG) * LL + l;
#pragma unroll
    for (int k = 0; k < KG; k++) pp[k * LL] = lg[k];
}

// ---------------------------------------------------------------------------
// K1b: combine partials + bias, softmax over k, write a (k<8) + asum partials.
// grid NB*2, block 256 (half an n's L per block).
// ---------------------------------------------------------------------------
__global__ __launch_bounds__(256) void k1b_softmax(const float* __restrict__ b)
{
    __shared__ float red[8][VK];
    const int tid  = threadIdx.x;
    const int lane = tid & 31;
    const int warp = tid >> 5;
    const int n    = blockIdx.x >> 1;
    const int half = blockIdx.x & 1;
    const int l    = half * 256 + tid;

    float lg[KG];
#pragma unroll
    for (int k = 0; k < KG; k++) lg[k] = __ldg(b + k);
#pragma unroll
    for (int cs = 0; cs < CS; cs++) {
        const float* pp = g_part + (((size_t)n * CS + cs) * KG) * LL + l;
#pragma unroll
        for (int k = 0; k < KG; k++) lg[k] += pp[k * LL];
    }

    float m = lg[0];
#pragma unroll
    for (int k = 1; k < KG; k++) m = fmaxf(m, lg[k]);
    float s = 0.f;
#pragma unroll
    for (int k = 0; k < KG; k++) { lg[k] = __expf(lg[k] - m); s += lg[k]; }
    float inv = 1.f / s;

    float* ap = g_a + ((size_t)n * VK) * LL + l;
#pragma unroll
    for (int k = 0; k < VK; k++) { lg[k] *= inv; ap[k * LL] = lg[k]; }

    // block-level deterministic assign_sum partial
#pragma unroll
    for (int k = 0; k < VK; k++) {
        float v = lg[k];
#pragma unroll
        for (int off = 16; off; off >>= 1) v += __shfl_down_sync(0xffffffffu, v, off);
        if (lane == 0) red[warp][k] = v;
    }
    __syncthreads();
    if (tid < VK) {
        float ss = 0.f;
#pragma unroll
        for (int w = 0; w < 8; w++) ss += red[w][tid];
        g_asum[(n * 2 + half) * VK + tid] = ss;
    }
}

// ---------------------------------------------------------------------------
// K2: assign_x partials over an l-half. grid (C/64, N, 2), block 256.
// Warp owns 8 c (two 4-c groups); fully unrolled j-loop batches 16 LDG.64.
// ---------------------------------------------------------------------------
__global__ __launch_bounds__(256) void k2_assign(const float* __restrict__ x)
{
    __shared__ float ash[VK * 256];   // 8 KB
    const int tid  = threadIdx.x;
    const int lane = tid & 31;
    const int warp = tid >> 5;
    const int n    = blockIdx.y;
    const int half = blockIdx.z;

    for (int i = tid; i < VK * 256; i += 256) {
        int k = i >> 8, ll = i & 255;
        ash[i] = g_a[((size_t)n * VK + k) * LL + half * 256 + ll];
    }
    __syncthreads();

    const int cbase = blockIdx.x * 64 + warp * 8;

#pragma unroll 1
    for (int g = 0; g < 2; g++) {
        const int c0 = cbase + g * 4;
        u64 acc[4][8];
#pragma unroll
        for (int ci = 0; ci < 4; ci++)
#pragma unroll
            for (int k = 0; k < 8; k++) acc[ci][k] = 0ull;

        const float* xb = x + ((size_t)n * CC + c0) * LL + half * 256;

#pragma unroll
        for (int j = 0; j < 4; j++) {
            const int l0 = j * 64 + lane * 2;
            u64 x2[4];
#pragma unroll
            for (int ci = 0; ci < 4; ci++) x2[ci] = *(const u64*)(xb + ci * LL + l0);
#pragma unroll
            for (int k = 0; k < 8; k++) {
                u64 a2 = *(const u64*)(ash + k * 256 + l0);
#pragma unroll
                for (int ci = 0; ci < 4; ci++) acc[ci][k] = ffma2(a2, x2[ci], acc[ci][k]);
            }
        }

#pragma unroll
        for (int ci = 0; ci < 4; ci++) {
#pragma unroll
            for (int k = 0; k < 8; k++) {
                float lo, hi; unpack2(acc[ci][k], lo, hi);
                float v = lo + hi;
#pragma unroll
                for (int off = 16; off; off >>= 1)
                    v += __shfl_down_sync(0xffffffffu, v, off);
                if (lane == 0)
                    g_axp[(((size_t)half * NB + n) * VK + k) * CC + c0 + ci] = v;
            }
        }
    }
}

// ---------------------------------------------------------------------------
// K3: residual vs centers, per-cluster L2 norm, global L2 norm.
// grid N, block 512 (thread = c).
// ---------------------------------------------------------------------------
__global__ __launch_bounds__(512) void k3_epilogue(
    const float* __restrict__ centers, float* __restrict__ out)
{
    __shared__ float asum_sh[VK];
    __shared__ float part[16][VK];
    __shared__ float scale_sh[VK];

    const int tid  = threadIdx.x;
    const int lane = tid & 31;
    const int warp = tid >> 5;
    const int n    = blockIdx.x;

    if (tid < VK)
        asum_sh[tid] = g_asum[(n * 2) * VK + tid] + g_asum[(n * 2 + 1) * VK + tid];
    __syncthreads();

    const int c = tid;
    float r[VK];
#pragma unroll
    for (int k = 0; k < VK; k++) {
        float ax = g_axp[(((size_t)0 * NB + n) * VK + k) * CC + c]
                 + g_axp[(((size_t)1 * NB + n) * VK + k) * CC + c];
        r[k] = ax - asum_sh[k] * centers[k * CC + c];
        float v = r[k] * r[k];
#pragma unroll
        for (int off = 16; off; off >>= 1) v += __shfl_down_sync(0xffffffffu, v, off);
        if (lane == 0) part[warp][k] = v;
    }
    __syncthreads();

    if (tid == 0) {
        float vlad = 0.f, sc[VK];
#pragma unroll
        for (int k = 0; k < VK; k++) {
            float ss = 0.f;
            for (int w = 0; w < 16; w++) ss += part[w][k];
            float nm = sqrtf(ss);
            float s1 = 1.f / fmaxf(nm, 1e-12f);
            sc[k] = s1;
            vlad += ss * s1 * s1;
        }
        float fs = 1.f / fmaxf(sqrtf(vlad), 1e-12f);
#pragma unroll
        for (int k = 0; k < VK; k++) scale_sh[k] = sc[k] * fs;
    }
    __syncthreads();

#pragma unroll
    for (int k = 0; k < VK; k++)
        out[(size_t)n * VK * CC + k * CC + c] = r[k] * scale_sh[k];
}

// ---------------------------------------------------------------------------
extern "C" void kernel_launch(void* const* d_in, const int* in_sizes, int n_in,
                              void* d_out, int out_size)
{
    const float* x       = (const float*)d_in[0];  // [32,512,16,32]
    const float* conv_w  = (const float*)d_in[1];  // [10,512]
    const float* conv_b  = (const float*)d_in[2];  // [10]
    const float* centers = (const float*)d_in[3];  // [10,512]
    float* out = (float*)d_out;                    // [32, 4096]

    k1_partial <<<dim3(LL / 128, NB, CS), 128>>>(x, conv_w);
    k1b_softmax<<<NB * 2, 256>>>(conv_b);
    k2_assign  <<<dim3(CC / 64, NB, 2), 256>>>(x);
    k3_epilogue<<<NB, 512>>>(centers, out);
}

// round 5
// speedup vs baseline: 1.6846x; 1.1096x over previous
#include <cuda_runtime.h>

#define NB   32
#define CC   512
#define LL   512
#define KG   10
#define VK   8
#define CS   4
#define CT   (CC/CS)   // 128

// Scratch (no allocations allowed)
__device__ float g_part[NB * CS * KG * LL];   // partial logits [n][cs][k][l]
__device__ float g_a   [NB * VK * LL];        // softmax assignments, k<8 [n][k][l]
__device__ float g_asum[NB * 2 * VK];         // per-half assign_sum partials
__device__ float g_axp [2 * NB * VK * CC];    // assign_x partials per l-half

typedef unsigned long long u64;

__device__ __forceinline__ u64 pack2(float lo, float hi) {
    u64 r; asm("mov.b64 %0,{%1,%2};" : "=l"(r) : "f"(lo), "f"(hi)); return r;
}
__device__ __forceinline__ void unpack2(u64 v, float& lo, float& hi) {
    asm("mov.b64 {%0,%1},%2;" : "=f"(lo), "=f"(hi) : "l"(v));
}
__device__ __forceinline__ u64 ffma2(u64 a, u64 b, u64 c) {
    u64 d; asm("fma.rn.f32x2 %0,%1,%2,%3;" : "=l"(d) : "l"(a), "l"(b), "l"(c)); return d;
}

// ---------------------------------------------------------------------------
// K1: partial logits over a 128-c slice. grid (L/256, N, CS), block 128.
// Each thread owns an l-pair; 16-wide LDG.64 batching for MLP.
// ---------------------------------------------------------------------------
__global__ __launch_bounds__(128) void k1_partial(
    const float* __restrict__ x, const float* __restrict__ w)
{
    __shared__ float wsh[CT * 12];   // [c][k], 12-float padded rows
    const int tid = threadIdx.x;
    const int n   = blockIdx.y;
    const int cs  = blockIdx.z;
    const int l0  = blockIdx.x * 256 + tid * 2;
    const int c0  = cs * CT;

    for (int i = tid; i < KG * CT; i += 128) {
        int k = i >> 7, c = i & (CT - 1);
        wsh[c * 12 + k] = w[k * CC + c0 + c];
    }
    __syncthreads();

    u64 accA[5], accB[5];
#pragma unroll
    for (int p = 0; p < 5; p++) { accA[p] = 0ull; accB[p] = 0ull; }

    const float* xp = x + ((size_t)n * CC + c0) * LL + l0;
#pragma unroll 1
    for (int cb = 0; cb < CT; cb += 16) {
        const float* xc = xp + (size_t)cb * LL;
        float2 xv[16];
#pragma unroll
        for (int i = 0; i < 16; i++) xv[i] = *(const float2*)(xc + i * LL);
#pragma unroll
        for (int i = 0; i < 16; i++) {
            u64 xa = pack2(xv[i].x, xv[i].x);
            u64 xb = pack2(xv[i].y, xv[i].y);
            const float* wr = wsh + (cb + i) * 12;
            u64 w0 = *(const u64*)(wr + 0);
            u64 w1 = *(const u64*)(wr + 2);
            u64 w2 = *(const u64*)(wr + 4);
            u64 w3 = *(const u64*)(wr + 6);
            u64 w4 = *(const u64*)(wr + 8);
            accA[0] = ffma2(w0, xa, accA[0]);  accB[0] = ffma2(w0, xb, accB[0]);
            accA[1] = ffma2(w1, xa, accA[1]);  accB[1] = ffma2(w1, xb, accB[1]);
            accA[2] = ffma2(w2, xa, accA[2]);  accB[2] = ffma2(w2, xb, accB[2]);
            accA[3] = ffma2(w3, xa, accA[3]);  accB[3] = ffma2(w3, xb, accB[3]);
            accA[4] = ffma2(w4, xa, accA[4]);  accB[4] = ffma2(w4, xb, accB[4]);
        }
    }

    float lgA[KG], lgB[KG];
#pragma unroll
    for (int p = 0; p < 5; p++) {
        unpack2(accA[p], lgA[2 * p], lgA[2 * p + 1]);
        unpack2(accB[p], lgB[2 * p], lgB[2 * p + 1]);
    }

    float* pp = g_part + (((size_t)n * CS + cs) * KG) * LL + l0;
#pragma unroll
    for (int k = 0; k < KG; k++) {
        float2 v; v.x = lgA[k]; v.y = lgB[k];
        *(float2*)(pp + k * LL) = v;
    }
}

// ---------------------------------------------------------------------------
// K1b: combine partials + bias, softmax over k, write a (k<8) + asum partials.
// grid NB*2, block 256 (half an n's L per block).
// ---------------------------------------------------------------------------
__global__ __launch_bounds__(256) void k1b_softmax(const float* __restrict__ b)
{
    __shared__ float red[8][VK];
    const int tid  = threadIdx.x;
    const int lane = tid & 31;
    const int warp = tid >> 5;
    const int n    = blockIdx.x >> 1;
    const int half = blockIdx.x & 1;
    const int l    = half * 256 + tid;

    float lg[KG];
#pragma unroll
    for (int k = 0; k < KG; k++) lg[k] = __ldg(b + k);
#pragma unroll
    for (int cs = 0; cs < CS; cs++) {
        const float* pp = g_part + (((size_t)n * CS + cs) * KG) * LL + l;
#pragma unroll
        for (int k = 0; k < KG; k++) lg[k] += pp[k * LL];
    }

    float m = lg[0];
#pragma unroll
    for (int k = 1; k < KG; k++) m = fmaxf(m, lg[k]);
    float s = 0.f;
#pragma unroll
    for (int k = 0; k < KG; k++) { lg[k] = __expf(lg[k] - m); s += lg[k]; }
    float inv = 1.f / s;

    float* ap = g_a + ((size_t)n * VK) * LL + l;
#pragma unroll
    for (int k = 0; k < VK; k++) { lg[k] *= inv; ap[k * LL] = lg[k]; }

    // block-level deterministic assign_sum partial
#pragma unroll
    for (int k = 0; k < VK; k++) {
        float v = lg[k];
#pragma unroll
        for (int off = 16; off; off >>= 1) v += __shfl_down_sync(0xffffffffu, v, off);
        if (lane == 0) red[warp][k] = v;
    }
    __syncthreads();
    if (tid < VK) {
        float ss = 0.f;
#pragma unroll
        for (int w = 0; w < 8; w++) ss += red[w][tid];
        g_asum[(n * 2 + half) * VK + tid] = ss;
    }
}

// ---------------------------------------------------------------------------
// K2: assign_x partials over an l-half. grid (C/64, N, 2), block 256.
// Warp owns 8 c (two 4-c groups); butterfly reduce-scatter for the epilogue.
// ---------------------------------------------------------------------------
__global__ __launch_bounds__(256) void k2_assign(const float* __restrict__ x)
{
    __shared__ float ash[VK * 256];   // 8 KB
    const int tid  = threadIdx.x;
    const int lane = tid & 31;
    const int warp = tid >> 5;
    const int n    = blockIdx.y;
    const int half = blockIdx.z;

    for (int i = tid; i < VK * 256; i += 256) {
        int k = i >> 8, ll = i & 255;
        ash[i] = g_a[((size_t)n * VK + k) * LL + half * 256 + ll];
    }
    __syncthreads();

    const int cbase = blockIdx.x * 64 + warp * 8;

#pragma unroll 1
    for (int g = 0; g < 2; g++) {
        const int c0 = cbase + g * 4;
        u64 acc[4][8];
#pragma unroll
        for (int ci = 0; ci < 4; ci++)
#pragma unroll
            for (int k = 0; k < 8; k++) acc[ci][k] = 0ull;

        const float* xb = x + ((size_t)n * CC + c0) * LL + half * 256;

#pragma unroll
        for (int j = 0; j < 4; j++) {
            const int l0 = j * 64 + lane * 2;
            u64 x2[4];
#pragma unroll
            for (int ci = 0; ci < 4; ci++) x2[ci] = *(const u64*)(xb + ci * LL + l0);
#pragma unroll
            for (int k = 0; k < 8; k++) {
                u64 a2 = *(const u64*)(ash + k * 256 + l0);
#pragma unroll
                for (int ci = 0; ci < 4; ci++) acc[ci][k] = ffma2(a2, x2[ci], acc[ci][k]);
            }
        }

        // Collapse l-pairs, then butterfly reduce-scatter: lane L ends up
        // holding the lane-sum of v[L] (index bit log2(o) <- lane bit).
        float v[32];
#pragma unroll
        for (int ci = 0; ci < 4; ci++)
#pragma unroll
            for (int k = 0; k < 8; k++) {
                float lo, hi; unpack2(acc[ci][k], lo, hi);
                v[ci * 8 + k] = lo + hi;
            }

#pragma unroll
        for (int o = 16; o >= 1; o >>= 1) {
            bool up = (lane & o) != 0;
#pragma unroll
            for (int i = 0; i < 32; i++) {
                if (i < o) {
                    float keep = up ? v[i + o] : v[i];
                    float send = up ? v[i] : v[i + o];
                    v[i] = keep + __shfl_xor_sync(0xffffffffu, send, o);
                }
            }
        }

        int ci = lane >> 3, k = lane & 7;
        g_axp[(((size_t)half * NB + n) * VK + k) * CC + c0 + ci] = v[0];
    }
}

// ---------------------------------------------------------------------------
// K3: residual vs centers, per-cluster L2 norm, global L2 norm — fully
// parallel epilogue. grid N, block 512 (thread = c).
// ---------------------------------------------------------------------------
__global__ __launch_bounds__(512) void k3_epilogue(
    const float* __restrict__ centers, float* __restrict__ out)
{
    __shared__ float asum_sh[VK];
    __shared__ float part[16][VK];
    __shared__ float scale_sh[VK];

    const int tid  = threadIdx.x;
    const int lane = tid & 31;
    const int warp = tid >> 5;
    const int n    = blockIdx.x;

    if (tid < VK)
        asum_sh[tid] = g_asum[(n * 2) * VK + tid] + g_asum[(n * 2 + 1) * VK + tid];
    __syncthreads();

    const int c = tid;
    float r[VK];
#pragma unroll
    for (int k = 0; k < VK; k++) {
        float ax = g_axp[(((size_t)0 * NB + n) * VK + k) * CC + c]
                 + g_axp[(((size_t)1 * NB + n) * VK + k) * CC + c];
        r[k] = ax - asum_sh[k] * centers[k * CC + c];
        float v = r[k] * r[k];
#pragma unroll
        for (int off = 16; off; off >>= 1) v += __shfl_down_sync(0xffffffffu, v, off);
        if (lane == 0) part[warp][k] = v;
    }
    __syncthreads();

    if (warp == 0) {
        int k = lane & 7;                    // lanes 8-31 duplicate k 0-7 (harmless)
        float ss = 0.f;
#pragma unroll
        for (int w = 0; w < 16; w++) ss += part[w][k];
        float nm = sqrtf(ss);
        float s1 = 1.f / fmaxf(nm, 1e-12f);
        float vlad = ss * s1 * s1;           // octet butterfly: sum over 8 k
        vlad += __shfl_xor_sync(0xffffffffu, vlad, 4);
        vlad += __shfl_xor_sync(0xffffffffu, vlad, 2);
        vlad += __shfl_xor_sync(0xffffffffu, vlad, 1);
        float fs = 1.f / fmaxf(sqrtf(vlad), 1e-12f);
        if (lane < 8) scale_sh[k] = s1 * fs;
    }
    __syncthreads();

#pragma unroll
    for (int k = 0; k < VK; k++)
        out[(size_t)n * VK * CC + k * CC + c] = r[k] * scale_sh[k];
}

// ---------------------------------------------------------------------------
extern "C" void kernel_launch(void* const* d_in, const int* in_sizes, int n_in,
                              void* d_out, int out_size)
{
    const float* x       = (const float*)d_in[0];  // [32,512,16,32]
    const float* conv_w  = (const float*)d_in[1];  // [10,512]
    const float* conv_b  = (const float*)d_in[2];  // [10]
    const float* centers = (const float*)d_in[3];  // [10,512]
    float* out = (float*)d_out;                    // [32, 4096]

    k1_partial <<<dim3(LL / 256, NB, CS), 128>>>(x, conv_w);
    k1b_softmax<<<NB * 2, 256>>>(conv_b);
    k2_assign  <<<dim3(CC / 64, NB, 2), 256>>>(x);
    k3_epilogue<<<NB, 512>>>(centers, out);
}

// round 6
// speedup vs baseline: 1.9424x; 1.1530x over previous
#include <cuda_runtime.h>

#define NB   32
#define CC   512
#define LL   512
#define KG   10
#define VK   8

// Scratch (no allocations allowed)
__device__ float g_a   [NB * VK * LL];        // softmax assignments, k<8 [n][k][l]
__device__ float g_asum[NB * 8 * VK];         // per-l-tile assign_sum partials
__device__ float g_axp [NB * VK * CC];        // assign_x [n][k][c]
__device__ int   g_ctr [NB];                  // arrival counters (zero-init, self-resetting)

typedef unsigned long long u64;

__device__ __forceinline__ u64 pack2(float lo, float hi) {
    u64 r; asm("mov.b64 %0,{%1,%2};" : "=l"(r) : "f"(lo), "f"(hi)); return r;
}
__device__ __forceinline__ void unpack2(u64 v, float& lo, float& hi) {
    asm("mov.b64 {%0,%1},%2;" : "=f"(lo), "=f"(hi) : "l"(v));
}
__device__ __forceinline__ u64 ffma2(u64 a, u64 b, u64 c) {
    u64 d; asm("fma.rn.f32x2 %0,%1,%2,%3;" : "=l"(d) : "l"(a), "l"(b), "l"(c)); return d;
}

// ---------------------------------------------------------------------------
// KA: logits + softmax + a + assign_sum partials, fused.
// grid (L/64, N), block 256. Warp w owns c-slice [64w, 64w+64) for the
// block's 64 l's (thread = l-pair). Cross-warp combine in smem, then
// 64 threads finish softmax; 2 warps produce the assign_sum partial.
// ---------------------------------------------------------------------------
__global__ __launch_bounds__(256) void ka_logits_softmax(
    const float* __restrict__ x, const float* __restrict__ w,
    const float* __restrict__ b)
{
    __shared__ float wsh[CC * 12];        // 24 KB, [c][k] 12-padded
    __shared__ float psh[8 * KG * 64];    // 20 KB, [warp][k][l_local]
    __shared__ float red[2][VK];

    const int tid   = threadIdx.x;
    const int lane  = tid & 31;
    const int warp  = tid >> 5;
    const int n     = blockIdx.y;
    const int lbase = blockIdx.x * 64;

    for (int i = tid; i < KG * CC; i += 256) {
        int k = i >> 9, c = i & (CC - 1);
        wsh[c * 12 + k] = w[i];
    }
    __syncthreads();

    u64 accA[5], accB[5];
#pragma unroll
    for (int p = 0; p < 5; p++) { accA[p] = 0ull; accB[p] = 0ull; }

    const int c0 = warp * 64;
    const float* xp = x + ((size_t)n * CC + c0) * LL + lbase + lane * 2;
#pragma unroll 1
    for (int cb = 0; cb < 64; cb += 16) {
        const float* xc = xp + (size_t)cb * LL;
        float2 xv[16];
#pragma unroll
        for (int i = 0; i < 16; i++) xv[i] = *(const float2*)(xc + i * LL);
#pragma unroll
        for (int i = 0; i < 16; i++) {
            u64 xa = pack2(xv[i].x, xv[i].x);
            u64 xb = pack2(xv[i].y, xv[i].y);
            const float* wr = wsh + (c0 + cb + i) * 12;
            u64 w0 = *(const u64*)(wr + 0);
            u64 w1 = *(const u64*)(wr + 2);
            u64 w2 = *(const u64*)(wr + 4);
            u64 w3 = *(const u64*)(wr + 6);
            u64 w4 = *(const u64*)(wr + 8);
            accA[0] = ffma2(w0, xa, accA[0]);  accB[0] = ffma2(w0, xb, accB[0]);
            accA[1] = ffma2(w1, xa, accA[1]);  accB[1] = ffma2(w1, xb, accB[1]);
            accA[2] = ffma2(w2, xa, accA[2]);  accB[2] = ffma2(w2, xb, accB[2]);
            accA[3] = ffma2(w3, xa, accA[3]);  accB[3] = ffma2(w3, xb, accB[3]);
            accA[4] = ffma2(w4, xa, accA[4]);  accB[4] = ffma2(w4, xb, accB[4]);
        }
    }

    // stash this warp's partial logits: psh[warp][k][l_local]
    {
        float lgA[KG], lgB[KG];
#pragma unroll
        for (int p = 0; p < 5; p++) {
            unpack2(accA[p], lgA[2 * p], lgA[2 * p + 1]);
            unpack2(accB[p], lgB[2 * p], lgB[2 * p + 1]);
        }
        float* pr = psh + (warp * KG) * 64 + lane * 2;
#pragma unroll
        for (int k = 0; k < KG; k++) {
            float2 v; v.x = lgA[k]; v.y = lgB[k];
            *(float2*)(pr + k * 64) = v;
        }
    }
    __syncthreads();

    // 64 threads (warps 0-1) finish: combine 8 warps, softmax, write a + asum
    if (tid < 64) {
        float lg[KG];
#pragma unroll
        for (int k = 0; k < KG; k++) lg[k] = __ldg(b + k);
#pragma unroll
        for (int wp = 0; wp < 8; wp++) {
            const float* pr = psh + (wp * KG) * 64 + tid;
#pragma unroll
            for (int k = 0; k < KG; k++) lg[k] += pr[k * 64];
        }

        float m = lg[0];
#pragma unroll
        for (int k = 1; k < KG; k++) m = fmaxf(m, lg[k]);
        float s = 0.f;
#pragma unroll
        for (int k = 0; k < KG; k++) { lg[k] = __expf(lg[k] - m); s += lg[k]; }
        float inv = 1.f / s;

        float* ap = g_a + ((size_t)n * VK) * LL + lbase + tid;
#pragma unroll
        for (int k = 0; k < VK; k++) { lg[k] *= inv; ap[k * LL] = lg[k]; }

        // octet reduce-scatter: lane ends with sum over its warp of lg[lane&7]
#pragma unroll
        for (int o = 4; o >= 1; o >>= 1) {
            bool up = (lane & o) != 0;
#pragma unroll
            for (int i = 0; i < 8; i++) {
                if (i < o) {
                    float keep = up ? lg[i + o] : lg[i];
                    float send = up ? lg[i] : lg[i + o];
                    lg[i] = keep + __shfl_xor_sync(0xffffffffu, send, o);
                }
            }
        }
        float t0 = lg[0];
        t0 += __shfl_xor_sync(0xffffffffu, t0, 8);
        t0 += __shfl_xor_sync(0xffffffffu, t0, 16);
        if (lane < 8) red[warp][lane] = t0;
    }
    __syncthreads();
    if (tid < VK)
        g_asum[((size_t)n * 8 + blockIdx.x) * VK + tid] = red[0][tid] + red[1][tid];
}

// ---------------------------------------------------------------------------
// KB: assign_x + (last block per n) full epilogue.
// grid (C/64, N), block 256. Warp owns 8 c over all 512 l.
// ---------------------------------------------------------------------------
__global__ __launch_bounds__(256) void kb_assign_epilogue(
    const float* __restrict__ x, const float* __restrict__ centers,
    float* __restrict__ out)
{
    __shared__ float ash[VK * LL];        // 16 KB
    __shared__ float asum_sh[VK];
    __shared__ float red2[8][VK];
    __shared__ float scale_sh[VK];
    __shared__ int   is_last;

    const int tid  = threadIdx.x;
    const int lane = tid & 31;
    const int warp = tid >> 5;
    const int n    = blockIdx.y;

    {   // coop copy a[n] (layout matches g_a slab) as float4
        const float4* src = (const float4*)(g_a + (size_t)n * VK * LL);
        float4* dst = (float4*)ash;
#pragma unroll
        for (int i = 0; i < 4; i++) dst[tid + i * 256] = src[tid + i * 256];
    }
    __syncthreads();

    const int cbase = blockIdx.x * 64 + warp * 8;

#pragma unroll 1
    for (int g = 0; g < 2; g++) {
        const int c0 = cbase + g * 4;
        u64 acc[4][8];
#pragma unroll
        for (int ci = 0; ci < 4; ci++)
#pragma unroll
            for (int k = 0; k < 8; k++) acc[ci][k] = 0ull;

        const float* xb = x + ((size_t)n * CC + c0) * LL;

#pragma unroll
        for (int j = 0; j < 8; j++) {
            const int l0 = j * 64 + lane * 2;
            u64 x2[4];
#pragma unroll
            for (int ci = 0; ci < 4; ci++) x2[ci] = *(const u64*)(xb + ci * LL + l0);
#pragma unroll
            for (int k = 0; k < 8; k++) {
                u64 a2 = *(const u64*)(ash + k * LL + l0);
#pragma unroll
                for (int ci = 0; ci < 4; ci++) acc[ci][k] = ffma2(a2, x2[ci], acc[ci][k]);
            }
        }

        float v[32];
#pragma unroll
        for (int ci = 0; ci < 4; ci++)
#pragma unroll
            for (int k = 0; k < 8; k++) {
                float lo, hi; unpack2(acc[ci][k], lo, hi);
                v[ci * 8 + k] = lo + hi;
            }

#pragma unroll
        for (int o = 16; o >= 1; o >>= 1) {
            bool up = (lane & o) != 0;
#pragma unroll
            for (int i = 0; i < 32; i++) {
                if (i < o) {
                    float keep = up ? v[i + o] : v[i];
                    float send = up ? v[i] : v[i + o];
                    v[i] = keep + __shfl_xor_sync(0xffffffffu, send, o);
                }
            }
        }

        int ci = lane >> 3, k = lane & 7;
        g_axp[((size_t)n * VK + k) * CC + c0 + ci] = v[0];
    }

    // ---- arrival: 8th block for this n runs the epilogue ----
    __syncthreads();
    if (tid == 0) {
        __threadfence();
        int old = atomicAdd(&g_ctr[n], 1);
        is_last = (old == 7);
    }
    __syncthreads();
    if (!is_last) return;
    __threadfence();

    if (tid < VK) {
        float s = 0.f;
#pragma unroll
        for (int blk = 0; blk < 8; blk++)
            s += g_asum[((size_t)n * 8 + blk) * VK + tid];
        asum_sh[tid] = s;
    }
    __syncthreads();

    // thread handles c = tid and tid+256
    float r0[VK], r1[VK], sq[VK];
    const int cA = tid, cB = tid + 256;
#pragma unroll
    for (int k = 0; k < VK; k++) {
        const float* axr = g_axp + ((size_t)n * VK + k) * CC;
        const float* cr  = centers + k * CC;
        r0[k] = axr[cA] - asum_sh[k] * cr[cA];
        r1[k] = axr[cB] - asum_sh[k] * cr[cB];
        sq[k] = r0[k] * r0[k] + r1[k] * r1[k];
    }

    // octet reduce-scatter within warp, then cross-warp via smem
#pragma unroll
    for (int o = 4; o >= 1; o >>= 1) {
        bool up = (lane & o) != 0;
#pragma unroll
        for (int i = 0; i < 8; i++) {
            if (i < o) {
                float keep = up ? sq[i + o] : sq[i];
                float send = up ? sq[i] : sq[i + o];
                sq[i] = keep + __shfl_xor_sync(0xffffffffu, send, o);
            }
        }
    }
    {
        float t0 = sq[0];
        t0 += __shfl_xor_sync(0xffffffffu, t0, 8);
        t0 += __shfl_xor_sync(0xffffffffu, t0, 16);
        if (lane < 8) red2[warp][lane] = t0;
    }
    __syncthreads();

    if (warp == 0) {
        int k = lane & 7;
        float ss = 0.f;
#pragma unroll
        for (int wp = 0; wp < 8; wp++) ss += red2[wp][k];
        float s1 = 1.f / fmaxf(sqrtf(ss), 1e-12f);
        float vlad = ss * s1 * s1;
        vlad += __shfl_xor_sync(0xffffffffu, vlad, 4);
        vlad += __shfl_xor_sync(0xffffffffu, vlad, 2);
        vlad += __shfl_xor_sync(0xffffffffu, vlad, 1);
        float fs = 1.f / fmaxf(sqrtf(vlad), 1e-12f);
        if (lane < 8) scale_sh[k] = s1 * fs;
    }
    __syncthreads();

#pragma unroll
    for (int k = 0; k < VK; k++) {
        float* o = out + (size_t)n * VK * CC + k * CC;
        o[cA] = r0[k] * scale_sh[k];
        o[cB] = r1[k] * scale_sh[k];
    }

    if (tid == 0) g_ctr[n] = 0;   // re-arm for next replay
}

// ---------------------------------------------------------------------------
extern "C" void kernel_launch(void* const* d_in, const int* in_sizes, int n_in,
                              void* d_out, int out_size)
{
    const float* x       = (const float*)d_in[0];  // [32,512,16,32]
    const float* conv_w  = (const float*)d_in[1];  // [10,512]
    const float* conv_b  = (const float*)d_in[2];  // [10]
    const float* centers = (const float*)d_in[3];  // [10,512]
    float* out = (float*)d_out;                    // [32, 4096]

    ka_logits_softmax <<<dim3(LL / 64, NB), 256>>>(x, conv_w, conv_b);
    kb_assign_epilogue<<<dim3(CC / 64, NB), 256>>>(x, centers, out);
}

// round 7
// speedup vs baseline: 2.4367x; 1.2545x over previous
#include <cuda_runtime.h>

#define NB   32
#define CC   512
#define LL   512
#define KG   10
#define VK   8

// Scratch (no allocations allowed)
__device__ float g_a   [NB * LL * VK];        // softmax assignments [n][l][k], k<8
__device__ float g_asum[NB * 8 * VK];         // per-l-tile assign_sum partials
__device__ float g_axp [NB * VK * CC];        // assign_x [n][k][c]
__device__ int   g_ctr [NB];                  // arrival counters (zero-init, self-resetting)

typedef unsigned long long u64;

__device__ __forceinline__ u64 pack2(float lo, float hi) {
    u64 r; asm("mov.b64 %0,{%1,%2};" : "=l"(r) : "f"(lo), "f"(hi)); return r;
}
__device__ __forceinline__ void unpack2(u64 v, float& lo, float& hi) {
    asm("mov.b64 {%0,%1},%2;" : "=f"(lo), "=f"(hi) : "l"(v));
}
__device__ __forceinline__ u64 ffma2(u64 a, u64 b, u64 c) {
    u64 d; asm("fma.rn.f32x2 %0,%1,%2,%3;" : "=l"(d) : "l"(a), "l"(b), "l"(c)); return d;
}

// ---------------------------------------------------------------------------
// KA: logits + softmax + a + assign_sum partials, fused.
// grid (L/64, N), block 256. Warp w owns c-slice [64w, 64w+64) for the
// block's 64 l's (thread = l-pair). Cross-warp combine in smem, then
// 64 threads finish softmax; writes a in [l][k] layout (2x float4/thread).
// ---------------------------------------------------------------------------
__global__ __launch_bounds__(256) void ka_logits_softmax(
    const float* __restrict__ x, const float* __restrict__ w,
    const float* __restrict__ b)
{
    __shared__ float wsh[CC * 12];        // 24 KB, [c][k] 12-padded
    __shared__ float psh[8 * KG * 64];    // 20 KB, [warp][k][l_local]
    __shared__ float red[2][VK];

    const int tid   = threadIdx.x;
    const int lane  = tid & 31;
    const int warp  = tid >> 5;
    const int n     = blockIdx.y;
    const int lbase = blockIdx.x * 64;

    for (int i = tid; i < KG * CC; i += 256) {
        int k = i >> 9, c = i & (CC - 1);
        wsh[c * 12 + k] = w[i];
    }
    __syncthreads();

    u64 accA[5], accB[5];
#pragma unroll
    for (int p = 0; p < 5; p++) { accA[p] = 0ull; accB[p] = 0ull; }

    const int c0 = warp * 64;
    const float* xp = x + ((size_t)n * CC + c0) * LL + lbase + lane * 2;
#pragma unroll 1
    for (int cb = 0; cb < 64; cb += 16) {
        const float* xc = xp + (size_t)cb * LL;
        float2 xv[16];
#pragma unroll
        for (int i = 0; i < 16; i++) xv[i] = *(const float2*)(xc + i * LL);
#pragma unroll
        for (int i = 0; i < 16; i++) {
            u64 xa = pack2(xv[i].x, xv[i].x);
            u64 xb = pack2(xv[i].y, xv[i].y);
            const float* wr = wsh + (c0 + cb + i) * 12;
            u64 w0 = *(const u64*)(wr + 0);
            u64 w1 = *(const u64*)(wr + 2);
            u64 w2 = *(const u64*)(wr + 4);
            u64 w3 = *(const u64*)(wr + 6);
            u64 w4 = *(const u64*)(wr + 8);
            accA[0] = ffma2(w0, xa, accA[0]);  accB[0] = ffma2(w0, xb, accB[0]);
            accA[1] = ffma2(w1, xa, accA[1]);  accB[1] = ffma2(w1, xb, accB[1]);
            accA[2] = ffma2(w2, xa, accA[2]);  accB[2] = ffma2(w2, xb, accB[2]);
            accA[3] = ffma2(w3, xa, accA[3]);  accB[3] = ffma2(w3, xb, accB[3]);
            accA[4] = ffma2(w4, xa, accA[4]);  accB[4] = ffma2(w4, xb, accB[4]);
        }
    }

    // stash this warp's partial logits: psh[warp][k][l_local]
    {
        float lgA[KG], lgB[KG];
#pragma unroll
        for (int p = 0; p < 5; p++) {
            unpack2(accA[p], lgA[2 * p], lgA[2 * p + 1]);
            unpack2(accB[p], lgB[2 * p], lgB[2 * p + 1]);
        }
        float* pr = psh + (warp * KG) * 64 + lane * 2;
#pragma unroll
        for (int k = 0; k < KG; k++) {
            float2 v; v.x = lgA[k]; v.y = lgB[k];
            *(float2*)(pr + k * 64) = v;
        }
    }
    __syncthreads();

    // 64 threads (warps 0-1) finish: combine 8 warps, softmax, write a + asum
    if (tid < 64) {
        float lg[KG];
#pragma unroll
        for (int k = 0; k < KG; k++) lg[k] = __ldg(b + k);
#pragma unroll
        for (int wp = 0; wp < 8; wp++) {
            const float* pr = psh + (wp * KG) * 64 + tid;
#pragma unroll
            for (int k = 0; k < KG; k++) lg[k] += pr[k * 64];
        }

        float m = lg[0];
#pragma unroll
        for (int k = 1; k < KG; k++) m = fmaxf(m, lg[k]);
        float s = 0.f;
#pragma unroll
        for (int k = 0; k < KG; k++) { lg[k] = __expf(lg[k] - m); s += lg[k]; }
        float inv = 1.f / s;

#pragma unroll
        for (int k = 0; k < VK; k++) lg[k] *= inv;

        // a in [n][l][k] layout: two coalesced float4 stores
        float* ap = g_a + ((size_t)n * LL + lbase + tid) * VK;
        *(float4*)(ap)     = make_float4(lg[0], lg[1], lg[2], lg[3]);
        *(float4*)(ap + 4) = make_float4(lg[4], lg[5], lg[6], lg[7]);

        // octet reduce-scatter: lane ends with sum over its warp of lg[lane&7]
#pragma unroll
        for (int o = 4; o >= 1; o >>= 1) {
            bool up = (lane & o) != 0;
#pragma unroll
            for (int i = 0; i < 8; i++) {
                if (i < o) {
                    float keep = up ? lg[i + o] : lg[i];
                    float send = up ? lg[i] : lg[i + o];
                    lg[i] = keep + __shfl_xor_sync(0xffffffffu, send, o);
                }
            }
        }
        float t0 = lg[0];
        t0 += __shfl_xor_sync(0xffffffffu, t0, 8);
        t0 += __shfl_xor_sync(0xffffffffu, t0, 16);
        if (lane < 8) red[warp][lane] = t0;
    }
    __syncthreads();
    if (tid < VK)
        g_asum[((size_t)n * 8 + blockIdx.x) * VK + tid] = red[0][tid] + red[1][tid];
}

// ---------------------------------------------------------------------------
// KB: assign_x + (last block per n) full epilogue.
// grid (C/32, N), block 256. Warp owns 4 c over all 512 l. k-pair-packed
// FFMA2 (a pairs from [l][k] smem via LDS.64, x broadcast) -> acc = 16 u64.
// ---------------------------------------------------------------------------
__global__ __launch_bounds__(256, 3) void kb_assign_epilogue(
    const float* __restrict__ x, const float* __restrict__ centers,
    float* __restrict__ out)
{
    __shared__ __align__(16) float ash[LL * 10];   // 20 KB, [l][k] pad to 10
    __shared__ float asum_sh[VK];
    __shared__ float red2[8][VK];
    __shared__ float scale_sh[VK];
    __shared__ int   is_last;

    const int tid  = threadIdx.x;
    const int lane = tid & 31;
    const int warp = tid >> 5;
    const int n    = blockIdx.y;

    {   // coop copy a[n] ([l][8] -> [l][10] padded), u64 granularity
        const u64* asrc = (const u64*)(g_a + (size_t)n * LL * VK);
#pragma unroll
        for (int i = tid; i < LL * 4; i += 256) {
            int l = i >> 2, kp = i & 3;
            *(u64*)(ash + l * 10 + kp * 2) = asrc[i];
        }
    }
    __syncthreads();

    const int c0 = blockIdx.x * 32 + warp * 4;

    u64 acc[4][4];
#pragma unroll
    for (int ci = 0; ci < 4; ci++)
#pragma unroll
        for (int kp = 0; kp < 4; kp++) acc[ci][kp] = 0ull;

    const float* xb = x + ((size_t)n * CC + c0) * LL;

#pragma unroll
    for (int j = 0; j < 8; j++) {
        const int lA = j * 64 + lane, lB = lA + 32;
        u64 aA[4], aB[4];
        float xA[4], xB[4];
#pragma unroll
        for (int kp = 0; kp < 4; kp++) {
            aA[kp] = *(const u64*)(ash + lA * 10 + kp * 2);
            aB[kp] = *(const u64*)(ash + lB * 10 + kp * 2);
        }
#pragma unroll
        for (int ci = 0; ci < 4; ci++) {
            xA[ci] = xb[ci * LL + lA];
            xB[ci] = xb[ci * LL + lB];
        }
#pragma unroll
        for (int ci = 0; ci < 4; ci++) {
            u64 xdA = pack2(xA[ci], xA[ci]);
            u64 xdB = pack2(xB[ci], xB[ci]);
#pragma unroll
            for (int kp = 0; kp < 4; kp++) {
                acc[ci][kp] = ffma2(aA[kp], xdA, acc[ci][kp]);
                acc[ci][kp] = ffma2(aB[kp], xdB, acc[ci][kp]);
            }
        }
    }

    // 32 outputs per thread -> butterfly reduce-scatter: lane L keeps v[L]
    {
        float v[32];
#pragma unroll
        for (int ci = 0; ci < 4; ci++)
#pragma unroll
            for (int kp = 0; kp < 4; kp++)
                unpack2(acc[ci][kp], v[ci * 8 + 2 * kp], v[ci * 8 + 2 * kp + 1]);

#pragma unroll
        for (int o = 16; o >= 1; o >>= 1) {
            bool up = (lane & o) != 0;
#pragma unroll
            for (int i = 0; i < 32; i++) {
                if (i < o) {
                    float keep = up ? v[i + o] : v[i];
                    float send = up ? v[i] : v[i + o];
                    v[i] = keep + __shfl_xor_sync(0xffffffffu, send, o);
                }
            }
        }

        int ci = lane >> 3, k = lane & 7;
        g_axp[((size_t)n * VK + k) * CC + c0 + ci] = v[0];
    }

    // ---- arrival: 16th block for this n runs the epilogue ----
    __syncthreads();
    if (tid == 0) {
        __threadfence();
        int old = atomicAdd(&g_ctr[n], 1);
        is_last = (old == 15);
    }
    __syncthreads();
    if (!is_last) return;
    __threadfence();

    if (tid < VK) {
        float s = 0.f;
#pragma unroll
        for (int blk = 0; blk < 8; blk++)
            s += g_asum[((size_t)n * 8 + blk) * VK + tid];
        asum_sh[tid] = s;
    }
    __syncthreads();

    // thread handles c = tid and tid+256
    float r0[VK], r1[VK], sq[VK];
    const int cA = tid, cB = tid + 256;
#pragma unroll
    for (int k = 0; k < VK; k++) {
        const float* axr = g_axp + ((size_t)n * VK + k) * CC;
        const float* cr  = centers + k * CC;
        r0[k] = axr[cA] - asum_sh[k] * cr[cA];
        r1[k] = axr[cB] - asum_sh[k] * cr[cB];
        sq[k] = r0[k] * r0[k] + r1[k] * r1[k];
    }

    // octet reduce-scatter within warp, then cross-warp via smem
#pragma unroll
    for (int o = 4; o >= 1; o >>= 1) {
        bool up = (lane & o) != 0;
#pragma unroll
        for (int i = 0; i < 8; i++) {
            if (i < o) {
                float keep = up ? sq[i + o] : sq[i];
                float send = up ? sq[i] : sq[i + o];
                sq[i] = keep + __shfl_xor_sync(0xffffffffu, send, o);
            }
        }
    }
    {
        float t0 = sq[0];
        t0 += __shfl_xor_sync(0xffffffffu, t0, 8);
        t0 += __shfl_xor_sync(0xffffffffu, t0, 16);
        if (lane < 8) red2[warp][lane] = t0;
    }
    __syncthreads();

    if (warp == 0) {
        int k = lane & 7;
        float ss = 0.f;
#pragma unroll
        for (int wp = 0; wp < 8; wp++) ss += red2[wp][k];
        float s1 = 1.f / fmaxf(sqrtf(ss), 1e-12f);
        float vlad = ss * s1 * s1;
        vlad += __shfl_xor_sync(0xffffffffu, vlad, 4);
        vlad += __shfl_xor_sync(0xffffffffu, vlad, 2);
        vlad += __shfl_xor_sync(0xffffffffu, vlad, 1);
        float fs = 1.f / fmaxf(sqrtf(vlad), 1e-12f);
        if (lane < 8) scale_sh[k] = s1 * fs;
    }
    __syncthreads();

#pragma unroll
    for (int k = 0; k < VK; k++) {
        float* o = out + (size_t)n * VK * CC + k * CC;
        o[cA] = r0[k] * scale_sh[k];
        o[cB] = r1[k] * scale_sh[k];
    }

    if (tid == 0) g_ctr[n] = 0;   // re-arm for next replay
}

// ---------------------------------------------------------------------------
extern "C" void kernel_launch(void* const* d_in, const int* in_sizes, int n_in,
                              void* d_out, int out_size)
{
    const float* x       = (const float*)d_in[0];  // [32,512,16,32]
    const float* conv_w  = (const float*)d_in[1];  // [10,512]
    const float* conv_b  = (const float*)d_in[2];  // [10]
    const float* centers = (const float*)d_in[3];  // [10,512]
    float* out = (float*)d_out;                    // [32, 4096]

    ka_logits_softmax <<<dim3(LL / 64, NB), 256>>>(x, conv_w, conv_b);
    kb_assign_epilogue<<<dim3(CC / 32, NB), 256>>>(x, centers, out);
}